// round 10
// baseline (speedup 1.0000x reference)
#include <cuda_runtime.h>

#define HD      768
#define SEQ     256
#define BATCH   4
#define ROWS    1024
#define NP      54
#define THRESH  0.5f
#define ROWOUT  (SEQ * NP)          // 13824
#define CROWS   (ROWS * HD)         // 786432 floats per split buffer

typedef unsigned long long u64;

// Scratch (device globals — no allocation allowed)
__device__ float g_c[3 * CROWS];         // split-K partials of x @ W1s^T (9.4 MB)
__device__ float g_hab[ROWS * 2 * HD];   // [row][ha | hb], candidate rows only
__device__ int   g_cand[ROWS];
__device__ int   g_rows[ROWS];
__device__ int   g_pairs[BATCH * SEQ * SEQ];
__device__ int   g_cnt;
__device__ int   g_nrows;

__device__ __forceinline__ void fma2(u64& d, u64 a, u64 b) {
    asm("fma.rn.f32x2 %0, %1, %2, %0;" : "+l"(d) : "l"(a), "l"(b));
}
__device__ __forceinline__ u64 dup2(float a) {
    u64 r; asm("mov.b64 %0, {%1, %1};" : "=l"(r) : "f"(a)); return r;
}
__device__ __forceinline__ void unpack2(float& lo, float& hi, u64 v) {
    asm("mov.b64 {%0, %1}, %2;" : "=f"(lo), "=f"(hi) : "l"(v));
}

// ---------------------------------------------------------------------------
// GEMM: partial c = x[:, ks:ks+256] @ W1s[:, ks:ks+256]^T  -> g_c[split]
// BM=128, BN=64, BK=16, 256 threads, m-pair packed FFMA2, split-K = 3.
// Trickles the 56.6MB output zero-fill through the k-loop.
// ---------------------------------------------------------------------------
#define BM 128
#define BN 64
#define BK 16
#define KSPLIT 256
#define LDA 132
#define LDB 68

__global__ void __launch_bounds__(256, 2) gemm_kernel(
    const float* __restrict__ X,
    const float* __restrict__ W1s,
    float* __restrict__ out)
{
    __shared__ float As[2][BK * LDA];
    __shared__ float Bs[2][BK * LDB];

    const int tid = threadIdx.x;
    const int n0 = blockIdx.x * BN;
    const int m0 = blockIdx.y * BM;
    const int ks = blockIdx.z * KSPLIT;
    const int ty = tid >> 4;
    const int tx = tid & 15;

    const int ctaid = blockIdx.z * 96 + blockIdx.y * 12 + blockIdx.x;  // 0..287
    if (ctaid == 0 && tid == 0) { g_nrows = 0; g_cnt = 0; }
    float4* o4 = (float4*)out + ctaid * 12288 + tid;

    const int am  = tid >> 2;
    const int akq = (tid & 3) * 4;
    const int bn  = tid & 63;
    const int bkq = (tid >> 6) * 4;

    const float* gA0 = X + (m0 + am) * HD + ks + akq;
    const float* gA1 = gA0 + 64 * HD;
    const float* gB  = W1s + (n0 + bn) * HD + ks + bkq;

    u64 acc[4][4];
    #pragma unroll
    for (int j = 0; j < 4; j++)
        #pragma unroll
        for (int ip = 0; ip < 4; ip++) acc[j][ip] = 0ull;

    float4 ra0, ra1, rb;

    ra0 = *(const float4*)gA0;
    ra1 = *(const float4*)gA1;
    rb  = *(const float4*)gB;
    {
        As[0][(akq+0)*LDA + am]      = ra0.x;  As[0][(akq+1)*LDA + am]      = ra0.y;
        As[0][(akq+2)*LDA + am]      = ra0.z;  As[0][(akq+3)*LDA + am]      = ra0.w;
        As[0][(akq+0)*LDA + am + 64] = ra1.x;  As[0][(akq+1)*LDA + am + 64] = ra1.y;
        As[0][(akq+2)*LDA + am + 64] = ra1.z;  As[0][(akq+3)*LDA + am + 64] = ra1.w;
        Bs[0][(bkq+0)*LDB + bn] = rb.x;  Bs[0][(bkq+1)*LDB + bn] = rb.y;
        Bs[0][(bkq+2)*LDB + bn] = rb.z;  Bs[0][(bkq+3)*LDB + bn] = rb.w;
    }
    ra0 = *(const float4*)(gA0 + BK);
    ra1 = *(const float4*)(gA1 + BK);
    rb  = *(const float4*)(gB  + BK);

    const int NITER = KSPLIT / BK;   // 16
    const float4 z4 = make_float4(0.f, 0.f, 0.f, 0.f);

    for (int it = 0; it < NITER; it++) {
        __syncthreads();
        const int cb = it & 1;

        o4[(it * 3 + 0) * 256] = z4;
        o4[(it * 3 + 1) * 256] = z4;
        o4[(it * 3 + 2) * 256] = z4;

        #pragma unroll
        for (int k = 0; k < BK; k++) {
            ulonglong2 a01 = *(const ulonglong2*)&As[cb][k * LDA + ty * 8];
            ulonglong2 a23 = *(const ulonglong2*)&As[cb][k * LDA + ty * 8 + 4];
            float4 bf = *(const float4*)&Bs[cb][k * LDB + tx * 4];
            u64 ap[4] = {a01.x, a01.y, a23.x, a23.y};
            u64 bd[4] = {dup2(bf.x), dup2(bf.y), dup2(bf.z), dup2(bf.w)};
            #pragma unroll
            for (int j = 0; j < 4; j++)
                #pragma unroll
                for (int ip = 0; ip < 4; ip++)
                    fma2(acc[j][ip], ap[ip], bd[j]);
        }

        if (it + 1 < NITER) {
            const int sb = (it + 1) & 1;
            As[sb][(akq+0)*LDA + am]      = ra0.x;  As[sb][(akq+1)*LDA + am]      = ra0.y;
            As[sb][(akq+2)*LDA + am]      = ra0.z;  As[sb][(akq+3)*LDA + am]      = ra0.w;
            As[sb][(akq+0)*LDA + am + 64] = ra1.x;  As[sb][(akq+1)*LDA + am + 64] = ra1.y;
            As[sb][(akq+2)*LDA + am + 64] = ra1.z;  As[sb][(akq+3)*LDA + am + 64] = ra1.w;
            Bs[sb][(bkq+0)*LDB + bn] = rb.x;  Bs[sb][(bkq+1)*LDB + bn] = rb.y;
            Bs[sb][(bkq+2)*LDB + bn] = rb.z;  Bs[sb][(bkq+3)*LDB + bn] = rb.w;
            if (it + 2 < NITER) {
                int ko = (it + 2) * BK;
                ra0 = *(const float4*)(gA0 + ko);
                ra1 = *(const float4*)(gA1 + ko);
                rb  = *(const float4*)(gB  + ko);
            }
        }
    }

    float cv[8][4];
    #pragma unroll
    for (int j = 0; j < 4; j++)
        #pragma unroll
        for (int ip = 0; ip < 4; ip++)
            unpack2(cv[2*ip][j], cv[2*ip+1][j], acc[j][ip]);

    float* cb = g_c + blockIdx.z * CROWS;
    #pragma unroll
    for (int i = 0; i < 8; i++) {
        int m = m0 + ty * 8 + i;
        *(float4*)&cb[m * HD + n0 + tx * 4] =
            make_float4(cv[i][0], cv[i][1], cv[i][2], cv[i][3]);
    }
}

// ---------------------------------------------------------------------------
// CAND: warp per row: span = sum_n relu(c0+c1+c2 + b1s)*W2s[0] + b2s[0]
// Builds the candidate row list directly.
// ---------------------------------------------------------------------------
__global__ void __launch_bounds__(256) cand_kernel(
    const float* __restrict__ b1s,
    const float* __restrict__ W2s,
    const float* __restrict__ b2s)
{
    const int row  = (blockIdx.x * 256 + threadIdx.x) >> 5;
    const int lane = threadIdx.x & 31;
    float s = 0.f;
    #pragma unroll
    for (int t = 0; t < HD / 32; t++) {
        int k = lane + 32 * t;
        float c = g_c[row * HD + k] + g_c[CROWS + row * HD + k]
                + g_c[2 * CROWS + row * HD + k];
        s += fmaxf(c + b1s[k], 0.f) * W2s[k];
    }
    #pragma unroll
    for (int o = 16; o > 0; o >>= 1)
        s += __shfl_xor_sync(0xffffffffu, s, o);
    if (lane == 0) {
        int c = (s + b2s[0]) > THRESH ? 1 : 0;
        g_cand[row] = c;
        if (c) {
            int r = atomicAdd(&g_nrows, 1);
            g_rows[r] = row;
        }
    }
}

// ---------------------------------------------------------------------------
// COMPACT: one block per batch; segment-reserve then fill pair codes.
// ---------------------------------------------------------------------------
__global__ void __launch_bounds__(SEQ) compact_kernel()
{
    __shared__ int fc[SEQ];
    const int b = blockIdx.x;
    const int t = threadIdx.x;
    fc[t] = g_cand[b * SEQ + t];
    __syncthreads();
    if (fc[t]) {
        int cnt = 0;
        for (int j = 0; j < SEQ; j++)
            if (fc[j] && j != t) cnt++;
        if (cnt) {
            int p = atomicAdd(&g_cnt, cnt);
            for (int j = 0; j < SEQ; j++)
                if (fc[j] && j != t)
                    g_pairs[p++] = (b * SEQ + t) * SEQ + j;   // rowi*256 + j
        }
    }
}

// ---------------------------------------------------------------------------
// HAB: one WARP per (candidate row, 4-col group).
// ---------------------------------------------------------------------------
__global__ void __launch_bounds__(256) hab_kernel(
    const float* __restrict__ X,
    const float* __restrict__ Wp1)
{
    const int lane   = threadIdx.x & 31;
    const int gwarp  = (blockIdx.x * 256 + threadIdx.x) >> 5;
    const int nwarps = gridDim.x * 8;
    const int total  = g_nrows * 384;

    for (int item = gwarp; item < total; item += nwarps) {
        const int rs  = item / 384;
        const int c0  = (item - rs * 384) * 4;
        const int row = g_rows[rs];
        const float* xr = X + row * HD;
        const float* wbase = (c0 < HD) ? (Wp1 + (size_t)c0 * (2 * HD))
                                       : (Wp1 + (size_t)(c0 - HD) * (2 * HD) + HD);
        float s0 = 0.f, s1 = 0.f, s2 = 0.f, s3 = 0.f;
        #pragma unroll
        for (int t = 0; t < HD / 32; t++) {
            int k = lane + 32 * t;
            float xv = __ldg(&xr[k]);
            s0 += xv * __ldg(&wbase[k]);
            s1 += xv * __ldg(&wbase[k + 2 * HD]);
            s2 += xv * __ldg(&wbase[k + 4 * HD]);
            s3 += xv * __ldg(&wbase[k + 6 * HD]);
        }
        #pragma unroll
        for (int o = 16; o > 0; o >>= 1) {
            s0 += __shfl_xor_sync(0xffffffffu, s0, o);
            s1 += __shfl_xor_sync(0xffffffffu, s1, o);
            s2 += __shfl_xor_sync(0xffffffffu, s2, o);
            s3 += __shfl_xor_sync(0xffffffffu, s3, o);
        }
        if (lane == 0)
            *(float4*)&g_hab[(size_t)row * (2 * HD) + c0] =
                make_float4(s0, s1, s2, s3);
    }
}

// ---------------------------------------------------------------------------
// PAIR_GEMM: tiled GEMM over the pair list.
// Block = 8 pairs x 54 logits; K streamed in 12 tiles of 64.
// V = relu(ha_i + hb_j + bp1) built in smem; Wp2 tile staged in smem
// (read once per 8 pairs). warp = pair, lane = logit (+32). No shuffles.
// ---------------------------------------------------------------------------
#define PB 8
#define LDW 65

__global__ void __launch_bounds__(256) pair_gemm_kernel(
    const float* __restrict__ bp1,
    const float* __restrict__ Wp2,
    const float* __restrict__ bp2,
    float* __restrict__ out)
{
    __shared__ float Vs[PB][LDW];
    __shared__ float Ws[NP][LDW];
    __shared__ int   codes[PB];

    const int tid   = threadIdx.x;
    const int wpair = tid >> 5;     // 0..7 : pair within block
    const int ty    = tid & 31;     // logit lane
    const int cnt   = g_cnt;
    const int nblk  = (cnt + PB - 1) / PB;

    for (int blk = blockIdx.x; blk < nblk; blk += gridDim.x) {
        __syncthreads();            // prior iteration fully consumed
        if (tid < PB) {
            int idx = blk * PB + tid;
            codes[tid] = (idx < cnt) ? g_pairs[idx] : -1;
        }
        __syncthreads();

        const int code = codes[wpair];
        float acc0 = 0.f, acc1 = 0.f;

        for (int kt = 0; kt < 12; kt++) {
            const int k0 = kt * 64;
            __syncthreads();        // previous tile consumed

            // build V tile: 8 pairs x 64 k  (512 elems, 2 per thread)
            #pragma unroll
            for (int r = 0; r < 2; r++) {
                int e  = tid + r * 256;
                int p  = e >> 6;
                int kk = e & 63;
                int c  = codes[p];
                float val = 0.f;
                if (c >= 0) {
                    int ri = c >> 8;
                    int rj = (ri & ~255) | (c & 255);
                    int k  = k0 + kk;
                    val = fmaxf(g_hab[ri * (2 * HD) + k] +
                                g_hab[rj * (2 * HD) + HD + k] + bp1[k], 0.f);
                }
                Vs[p][kk] = val;
            }
            // stage Wp2 tile: 54 x 64
            for (int e = tid; e < NP * 64; e += 256) {
                int pp = e >> 6;
                int kk = e & 63;
                Ws[pp][kk] = Wp2[pp * HD + k0 + kk];
            }
            __syncthreads();

            #pragma unroll 16
            for (int kk = 0; kk < 64; kk++) {
                float a = Vs[wpair][kk];
                acc0 += a * Ws[ty][kk];
                if (ty < NP - 32) acc1 += a * Ws[ty + 32][kk];
            }
        }

        if (code >= 0) {
            float* o = out + (size_t)code * NP;   // code == rowi*SEQ + j
            o[ty] = acc0 + bp2[ty];
            if (ty < NP - 32) o[ty + 32] = acc1 + bp2[ty + 32];
        }
    }
}

// ---------------------------------------------------------------------------
extern "C" void kernel_launch(void* const* d_in, const int* in_sizes, int n_in,
                              void* d_out, int out_size)
{
    const float* x   = (const float*)d_in[0];
    const float* W1s = (const float*)d_in[1];
    const float* b1s = (const float*)d_in[2];
    const float* W2s = (const float*)d_in[3];
    const float* b2s = (const float*)d_in[4];
    const float* Wp1 = (const float*)d_in[5];
    const float* bp1 = (const float*)d_in[6];
    const float* Wp2 = (const float*)d_in[7];
    const float* bp2 = (const float*)d_in[8];
    float* out = (float*)d_out;

    // 1) split-K partial GEMM + fused output zero-fill + counter resets
    dim3 g1(HD / BN, ROWS / BM, 3);              // 288 CTAs, single wave
    gemm_kernel<<<g1, 256>>>(x, W1s, out);

    // 2) candidate mask + row list (warp per row)
    cand_kernel<<<ROWS / 8, 256>>>(b1s, W2s, b2s);

    // 3) pair list
    compact_kernel<<<BATCH, SEQ>>>();

    // 4) ha/hb: one warp per (row, 4-col group)
    hab_kernel<<<512, 256>>>(x, Wp1);

    // 5) pair logits as a tiled GEMM over the pair list
    pair_gemm_kernel<<<1024, 256>>>(bp1, Wp2, bp2, out);
}

// round 11
// speedup vs baseline: 1.4976x; 1.4976x over previous
#include <cuda_runtime.h>

#define HD      768
#define SEQ     256
#define BATCH   4
#define ROWS    1024
#define NP      54
#define THRESH  0.5f
#define ROWOUT  (SEQ * NP)          // 13824
#define CROWS   (ROWS * HD)         // 786432 floats per split buffer

typedef unsigned long long u64;

// Scratch (device globals — no allocation allowed)
__device__ float g_c[3 * CROWS];         // split-K partials of x @ W1s^T (9.4 MB)
__device__ float g_hab[ROWS * 2 * HD];   // [row][ha | hb], candidate rows only
__device__ int   g_cand[ROWS];
__device__ int   g_rows[ROWS];
__device__ int   g_nrows;

__device__ __forceinline__ void fma2(u64& d, u64 a, u64 b) {
    asm("fma.rn.f32x2 %0, %1, %2, %0;" : "+l"(d) : "l"(a), "l"(b));
}
__device__ __forceinline__ u64 dup2(float a) {
    u64 r; asm("mov.b64 %0, {%1, %1};" : "=l"(r) : "f"(a)); return r;
}
__device__ __forceinline__ void unpack2(float& lo, float& hi, u64 v) {
    asm("mov.b64 {%0, %1}, %2;" : "=f"(lo), "=f"(hi) : "l"(v));
}

// ---------------------------------------------------------------------------
// GEMM: partial c = x[:, ks:ks+256] @ W1s[:, ks:ks+256]^T  -> g_c[split]
// BM=128, BN=64, BK=16, 256 threads, m-pair packed FFMA2, split-K = 3.
// Trickles the 56.6MB output zero-fill through the k-loop.
// ---------------------------------------------------------------------------
#define BM 128
#define BN 64
#define BK 16
#define KSPLIT 256
#define LDA 132
#define LDB 68

__global__ void __launch_bounds__(256, 2) gemm_kernel(
    const float* __restrict__ X,
    const float* __restrict__ W1s,
    float* __restrict__ out)
{
    __shared__ float As[2][BK * LDA];
    __shared__ float Bs[2][BK * LDB];

    const int tid = threadIdx.x;
    const int n0 = blockIdx.x * BN;
    const int m0 = blockIdx.y * BM;
    const int ks = blockIdx.z * KSPLIT;
    const int ty = tid >> 4;
    const int tx = tid & 15;

    const int ctaid = blockIdx.z * 96 + blockIdx.y * 12 + blockIdx.x;  // 0..287
    if (ctaid == 0 && tid == 0) g_nrows = 0;
    float4* o4 = (float4*)out + ctaid * 12288 + tid;

    const int am  = tid >> 2;
    const int akq = (tid & 3) * 4;
    const int bn  = tid & 63;
    const int bkq = (tid >> 6) * 4;

    const float* gA0 = X + (m0 + am) * HD + ks + akq;
    const float* gA1 = gA0 + 64 * HD;
    const float* gB  = W1s + (n0 + bn) * HD + ks + bkq;

    u64 acc[4][4];
    #pragma unroll
    for (int j = 0; j < 4; j++)
        #pragma unroll
        for (int ip = 0; ip < 4; ip++) acc[j][ip] = 0ull;

    float4 ra0, ra1, rb;

    ra0 = *(const float4*)gA0;
    ra1 = *(const float4*)gA1;
    rb  = *(const float4*)gB;
    {
        As[0][(akq+0)*LDA + am]      = ra0.x;  As[0][(akq+1)*LDA + am]      = ra0.y;
        As[0][(akq+2)*LDA + am]      = ra0.z;  As[0][(akq+3)*LDA + am]      = ra0.w;
        As[0][(akq+0)*LDA + am + 64] = ra1.x;  As[0][(akq+1)*LDA + am + 64] = ra1.y;
        As[0][(akq+2)*LDA + am + 64] = ra1.z;  As[0][(akq+3)*LDA + am + 64] = ra1.w;
        Bs[0][(bkq+0)*LDB + bn] = rb.x;  Bs[0][(bkq+1)*LDB + bn] = rb.y;
        Bs[0][(bkq+2)*LDB + bn] = rb.z;  Bs[0][(bkq+3)*LDB + bn] = rb.w;
    }
    ra0 = *(const float4*)(gA0 + BK);
    ra1 = *(const float4*)(gA1 + BK);
    rb  = *(const float4*)(gB  + BK);

    const int NITER = KSPLIT / BK;   // 16
    const float4 z4 = make_float4(0.f, 0.f, 0.f, 0.f);

    for (int it = 0; it < NITER; it++) {
        __syncthreads();
        const int cb = it & 1;

        o4[(it * 3 + 0) * 256] = z4;
        o4[(it * 3 + 1) * 256] = z4;
        o4[(it * 3 + 2) * 256] = z4;

        #pragma unroll
        for (int k = 0; k < BK; k++) {
            ulonglong2 a01 = *(const ulonglong2*)&As[cb][k * LDA + ty * 8];
            ulonglong2 a23 = *(const ulonglong2*)&As[cb][k * LDA + ty * 8 + 4];
            float4 bf = *(const float4*)&Bs[cb][k * LDB + tx * 4];
            u64 ap[4] = {a01.x, a01.y, a23.x, a23.y};
            u64 bd[4] = {dup2(bf.x), dup2(bf.y), dup2(bf.z), dup2(bf.w)};
            #pragma unroll
            for (int j = 0; j < 4; j++)
                #pragma unroll
                for (int ip = 0; ip < 4; ip++)
                    fma2(acc[j][ip], ap[ip], bd[j]);
        }

        if (it + 1 < NITER) {
            const int sb = (it + 1) & 1;
            As[sb][(akq+0)*LDA + am]      = ra0.x;  As[sb][(akq+1)*LDA + am]      = ra0.y;
            As[sb][(akq+2)*LDA + am]      = ra0.z;  As[sb][(akq+3)*LDA + am]      = ra0.w;
            As[sb][(akq+0)*LDA + am + 64] = ra1.x;  As[sb][(akq+1)*LDA + am + 64] = ra1.y;
            As[sb][(akq+2)*LDA + am + 64] = ra1.z;  As[sb][(akq+3)*LDA + am + 64] = ra1.w;
            Bs[sb][(bkq+0)*LDB + bn] = rb.x;  Bs[sb][(bkq+1)*LDB + bn] = rb.y;
            Bs[sb][(bkq+2)*LDB + bn] = rb.z;  Bs[sb][(bkq+3)*LDB + bn] = rb.w;
            if (it + 2 < NITER) {
                int ko = (it + 2) * BK;
                ra0 = *(const float4*)(gA0 + ko);
                ra1 = *(const float4*)(gA1 + ko);
                rb  = *(const float4*)(gB  + ko);
            }
        }
    }

    float cv[8][4];
    #pragma unroll
    for (int j = 0; j < 4; j++)
        #pragma unroll
        for (int ip = 0; ip < 4; ip++)
            unpack2(cv[2*ip][j], cv[2*ip+1][j], acc[j][ip]);

    float* cb = g_c + blockIdx.z * CROWS;
    #pragma unroll
    for (int i = 0; i < 8; i++) {
        int m = m0 + ty * 8 + i;
        *(float4*)&cb[m * HD + n0 + tx * 4] =
            make_float4(cv[i][0], cv[i][1], cv[i][2], cv[i][3]);
    }
}

// ---------------------------------------------------------------------------
// CAND: warp per row: span = sum_n relu(c0+c1+c2 + b1s)*W2s[0] + b2s[0]
// Builds the candidate row list directly (order-invariant consumers).
// ---------------------------------------------------------------------------
__global__ void __launch_bounds__(256) cand_kernel(
    const float* __restrict__ b1s,
    const float* __restrict__ W2s,
    const float* __restrict__ b2s)
{
    const int row  = (blockIdx.x * 256 + threadIdx.x) >> 5;
    const int lane = threadIdx.x & 31;
    float s = 0.f;
    #pragma unroll
    for (int t = 0; t < HD / 32; t++) {
        int k = lane + 32 * t;
        float c = g_c[row * HD + k] + g_c[CROWS + row * HD + k]
                + g_c[2 * CROWS + row * HD + k];
        s += fmaxf(c + b1s[k], 0.f) * W2s[k];
    }
    #pragma unroll
    for (int o = 16; o > 0; o >>= 1)
        s += __shfl_xor_sync(0xffffffffu, s, o);
    if (lane == 0) {
        int c = (s + b2s[0]) > THRESH ? 1 : 0;
        g_cand[row] = c;
        if (c) {
            int r = atomicAdd(&g_nrows, 1);
            g_rows[r] = row;
        }
    }
}

// ---------------------------------------------------------------------------
// HAB: one WARP per (candidate row, output column). float4 loads: 6 LDG.128
// per operand instead of 24 LDG.32 — same bytes, deeper effective MLP.
// ---------------------------------------------------------------------------
__global__ void __launch_bounds__(256) hab_kernel(
    const float* __restrict__ X,
    const float* __restrict__ Wp1)
{
    const int lane   = threadIdx.x & 31;
    const int gwarp  = (blockIdx.x * 256 + threadIdx.x) >> 5;
    const int nwarps = gridDim.x * 8;
    const int total  = g_nrows * 1536;

    for (int item = gwarp; item < total; item += nwarps) {
        const int rs  = item / 1536;
        const int c   = item - rs * 1536;
        const int row = g_rows[rs];
        const float4* xr = (const float4*)(X + row * HD);
        const float* wr  = (c < HD) ? (Wp1 + (size_t)c * (2 * HD))
                                    : (Wp1 + (size_t)(c - HD) * (2 * HD) + HD);
        const float4* w4 = (const float4*)wr;
        float s = 0.f;
        #pragma unroll
        for (int t = 0; t < HD / 128; t++) {        // 6 iterations
            int k = lane + 32 * t;
            float4 xv = __ldg(&xr[k]);
            float4 wv = __ldg(&w4[k]);
            s += xv.x * wv.x + xv.y * wv.y + xv.z * wv.z + xv.w * wv.w;
        }
        #pragma unroll
        for (int o = 16; o > 0; o >>= 1)
            s += __shfl_xor_sync(0xffffffffu, s, o);
        if (lane == 0) g_hab[(size_t)row * (2 * HD) + c] = s;
    }
}

// ---------------------------------------------------------------------------
// PAIR: grid-stride blocks over (candidate slot, j); uniform early exit.
// Valid pair: each warp owns 7 logits with 7 CONCURRENT accumulators
// (independent load/FMA chains -> latency hidden), then 7 shuffle-reduces.
// ---------------------------------------------------------------------------
__global__ void __launch_bounds__(256) pair_kernel(
    const float* __restrict__ bp1,
    const float* __restrict__ Wp2,
    const float* __restrict__ bp2,
    float* __restrict__ out)
{
    __shared__ float v[HD];
    const int tid  = threadIdx.x;
    const int warp = tid >> 5;
    const int lane = tid & 31;
    const int total = g_nrows << 8;

    for (int it = blockIdx.x; it < total; it += gridDim.x) {
        const int slot = it >> 8;
        const int j    = it & 255;
        const int rowi = g_rows[slot];
        const int i    = rowi & 255;
        const int rowj = (rowi & ~255) | j;
        if (j == i || !g_cand[rowj]) continue;   // block-uniform

        __syncthreads();                          // v from prior item consumed
        for (int k = tid; k < HD; k += 256)
            v[k] = fmaxf(g_hab[(size_t)rowi * (2 * HD) + k] +
                         g_hab[(size_t)rowj * (2 * HD) + HD + k] + bp1[k], 0.f);
        __syncthreads();

        // warp w -> logits 7w .. 7w+6 (warp 7: 49..53 valid)
        const int p0 = warp * 7;
        float acc[7];
        #pragma unroll
        for (int q = 0; q < 7; q++) acc[q] = 0.f;

        #pragma unroll
        for (int t = 0; t < HD / 32; t++) {
            int k = lane + 32 * t;
            float vv = v[k];
            #pragma unroll
            for (int q = 0; q < 7; q++) {
                int pp = p0 + q;
                if (pp < NP)
                    acc[q] += vv * __ldg(&Wp2[pp * HD + k]);
            }
        }
        #pragma unroll
        for (int q = 0; q < 7; q++) {
            #pragma unroll
            for (int off = 16; off > 0; off >>= 1)
                acc[q] += __shfl_xor_sync(0xffffffffu, acc[q], off);
        }
        if (lane < 7) {
            int pp = p0 + lane;
            float s = __shfl_sync(0xffffffffu, acc[lane], 0);  // dummy keep
        }
        // lane 0 writes its warp's 7 logits
        if (lane == 0) {
            float* o = out + ((size_t)rowi * SEQ + j) * NP;
            #pragma unroll
            for (int q = 0; q < 7; q++) {
                int pp = p0 + q;
                if (pp < NP) o[pp] = acc[q] + bp2[pp];
            }
        }
    }
}

// ---------------------------------------------------------------------------
extern "C" void kernel_launch(void* const* d_in, const int* in_sizes, int n_in,
                              void* d_out, int out_size)
{
    const float* x   = (const float*)d_in[0];
    const float* W1s = (const float*)d_in[1];
    const float* b1s = (const float*)d_in[2];
    const float* W2s = (const float*)d_in[3];
    const float* b2s = (const float*)d_in[4];
    const float* Wp1 = (const float*)d_in[5];
    const float* bp1 = (const float*)d_in[6];
    const float* Wp2 = (const float*)d_in[7];
    const float* bp2 = (const float*)d_in[8];
    float* out = (float*)d_out;

    // 1) split-K partial GEMM + fused output zero-fill + counter reset
    dim3 g1(HD / BN, ROWS / BM, 3);              // 288 CTAs, single wave
    gemm_kernel<<<g1, 256>>>(x, W1s, out);

    // 2) candidate mask + row list (warp per row)
    cand_kernel<<<ROWS / 8, 256>>>(b1s, W2s, b2s);

    // 3) ha/hb: one warp per (row, col), float4 loads
    hab_kernel<<<1024, 256>>>(x, Wp1);

    // 4) pair logits: grid-stride (slot, j), 7-wide ILP dots
    pair_kernel<<<2048, 256>>>(bp1, Wp2, bp2, out);
}